// round 15
// baseline (speedup 1.0000x reference)
#include <cuda_runtime.h>
#include <cuda_bf16.h>
#include <math.h>
#include <stdint.h>

// ---------------- problem constants ----------------
#define N_ATOMS   20000
#define N_EDGES   640000
#define N_STRUCT  100
#define N_SPECIES 4
#define N_RADIAL  8
#define N_SPH     16
#define Q_DIM     32
#define C_PER_ATOM 512
#define PS_DIM    4096
#define NPAIR     528
#define PS_SYM    2112              // 66 * 32
#define HID       256
#define CUTOFF    5.0f
#define EPSR      1e-12f
#define MAX_TILES 160

// ---------------- scratch ----------------
__device__ float g_c  [(size_t)N_ATOMS * C_PER_ATOM];
__device__ __nv_bfloat16 g_psh[(size_t)N_ATOMS * PS_SYM];
__device__ __nv_bfloat16 g_psl[(size_t)N_ATOMS * PS_SYM];
__device__ __nv_bfloat16 g_h1h[(size_t)N_ATOMS * HID];
__device__ __nv_bfloat16 g_h1l[(size_t)N_ATOMS * HID];
__device__ __nv_bfloat16 g_w1h[(size_t)N_SPECIES * HID * PS_SYM];
__device__ __nv_bfloat16 g_w1l[(size_t)N_SPECIES * HID * PS_SYM];
__device__ __nv_bfloat16 g_w2h[(size_t)N_SPECIES * HID * HID];
__device__ __nv_bfloat16 g_w2l[(size_t)N_SPECIES * HID * HID];
__device__ int   g_pairq[NPAIR];
__device__ int   g_pairp[NPAIR];
__device__ int   g_counts[N_SPECIES];
__device__ int   g_off[N_SPECIES];
__device__ int   g_cursor[N_SPECIES];
__device__ int   g_sorted[N_ATOMS];

// ---------------- helpers ----------------
__device__ __forceinline__ float silu(float x) { return x / (1.0f + expf(-x)); }

__device__ __forceinline__ void red4(float* p, float a, float b, float c, float d) {
    asm volatile("red.global.add.v4.f32 [%0], {%1,%2,%3,%4};"
                 :: "l"(p), "f"(a), "f"(b), "f"(c), "f"(d) : "memory");
}

__device__ __forceinline__ uint32_t pack2(__nv_bfloat16 a, __nv_bfloat16 b) {
    return (uint32_t)__bfloat16_as_ushort(a) | ((uint32_t)__bfloat16_as_ushort(b) << 16);
}

__device__ __forceinline__ void mma_bf16(float& c0, float& c1, float& c2, float& c3,
                                         uint32_t a0, uint32_t a1, uint32_t a2, uint32_t a3,
                                         uint32_t b0, uint32_t b1) {
    asm volatile("mma.sync.aligned.m16n8k16.row.col.f32.bf16.bf16.f32 "
                 "{%0,%1,%2,%3}, {%4,%5,%6,%7}, {%8,%9}, {%0,%1,%2,%3};"
                 : "+f"(c0), "+f"(c1), "+f"(c2), "+f"(c3)
                 : "r"(a0), "r"(a1), "r"(a2), "r"(a3), "r"(b0), "r"(b1));
}

__device__ __forceinline__ void ldmatrix_x4(uint32_t& r0, uint32_t& r1,
                                            uint32_t& r2, uint32_t& r3, uint32_t addr) {
    asm volatile("ldmatrix.sync.aligned.m8n8.x4.shared.b16 {%0,%1,%2,%3}, [%4];"
                 : "=r"(r0), "=r"(r1), "=r"(r2), "=r"(r3) : "r"(addr));
}

__device__ __forceinline__ void cp_async16(uint32_t dst, const void* src, int src_bytes) {
    asm volatile("cp.async.cg.shared.global [%0], [%1], 16, %2;"
                 :: "r"(dst), "l"(src), "r"(src_bytes) : "memory");
}
#define CP_COMMIT() asm volatile("cp.async.commit_group;" ::: "memory")
#define CP_WAIT(n)  asm volatile("cp.async.wait_group %0;" :: "n"(n) : "memory")

// ---------------- K0: zero g_c + out, build pair table (block 0) ----------------
__global__ void zero_kernel(float* __restrict__ out) {
    size_t idx = (size_t)blockIdx.x * blockDim.x + threadIdx.x;
    float4* c4 = reinterpret_cast<float4*>(g_c);
    c4[idx] = make_float4(0.f, 0.f, 0.f, 0.f);
    if (idx < N_STRUCT) out[idx] = 0.f;
    if (blockIdx.x == 0) {
        for (int i = threadIdx.x; i < NPAIR; i += blockDim.x) {
            int q = 0, off = 0;
            while (off + (Q_DIM - q) <= i) { off += Q_DIM - q; q++; }
            g_pairq[i] = q;
            g_pairp[i] = q + (i - off);
        }
    }
}

// ---------------- K0c: zero species counters (placed AFTER sacrificial gemm) ----------------
__global__ void zero_counts_kernel() {
    if (threadIdx.x < N_SPECIES) g_counts[threadIdx.x] = 0;
}

// ---------------- K1 ----------------
__global__ void atom_prep_kernel(const int* __restrict__ numbers,
                                 const int* __restrict__ batch,
                                 const float* __restrict__ Wc,
                                 float* __restrict__ out) {
    int a = blockIdx.x * blockDim.x + threadIdx.x;
    if (a >= N_ATOMS) return;
    int s = numbers[a];
    atomicAdd(&g_counts[s], 1);
    atomicAdd(&out[batch[a]], Wc[s]);
}

// ---------------- K2: scan only ----------------
__global__ void offsets_kernel() {
    if (threadIdx.x == 0) {
        int acc = 0;
        for (int s = 0; s < N_SPECIES; s++) {
            g_off[s] = acc;
            g_cursor[s] = acc;
            acc += g_counts[s];
        }
    }
}

// ---------------- K3 ----------------
__global__ void scatter_kernel(const int* __restrict__ numbers) {
    int a = blockIdx.x * blockDim.x + threadIdx.x;
    if (a >= N_ATOMS) return;
    int s = numbers[a];
    int pos = atomicAdd(&g_cursor[s], 1);
    g_sorted[pos] = a;
}

// ---------------- K3b: fold W1 + transpose + split ----------------
__global__ void fold_w1_kernel(const float* __restrict__ W1) {
    __shared__ float tile[32][33];
    int tx = threadIdx.x, ty = threadIdx.y;
    int k = blockIdx.x * 32 + ty;
    int n = blockIdx.y * 32 + tx;
    int l  = k / NPAIR;
    int pr = k - l * NPAIR;
    int q = g_pairq[pr], p = g_pairp[pr];
    const float* Ws = W1 + (size_t)blockIdx.z * PS_DIM * HID;
    float v = Ws[(size_t)(l * 1024 + q * 32 + p) * HID + n];
    if (q != p)
        v += Ws[(size_t)(l * 1024 + p * 32 + q) * HID + n];
    tile[ty][tx] = v;
    __syncthreads();
    int nn = blockIdx.y * 32 + ty;
    int kk = blockIdx.x * 32 + tx;
    float w = tile[tx][ty];
    __nv_bfloat16 h = __float2bfloat16_rn(w);
    size_t oi = ((size_t)(blockIdx.z * HID + nn)) * PS_SYM + kk;
    g_w1h[oi] = h;
    g_w1l[oi] = __float2bfloat16_rn(w - __bfloat162float(h));
}

// ---------------- K3c: W2 transpose + split ----------------
__global__ void fold_w2_kernel(const float* __restrict__ W2) {
    __shared__ float tile[32][33];
    int tx = threadIdx.x, ty = threadIdx.y;
    int k = blockIdx.x * 32 + ty;
    int n = blockIdx.y * 32 + tx;
    tile[ty][tx] = W2[((size_t)(blockIdx.z * HID + k)) * HID + n];
    __syncthreads();
    int nn = blockIdx.y * 32 + ty;
    int kk = blockIdx.x * 32 + tx;
    float w = tile[tx][ty];
    __nv_bfloat16 h = __float2bfloat16_rn(w);
    size_t oi = ((size_t)(blockIdx.z * HID + nn)) * HID + kk;
    g_w2h[oi] = h;
    g_w2l[oi] = __float2bfloat16_rn(w - __bfloat162float(h));
}

// ---------------- K4: edge featurization ----------------
__global__ void edge_kernel(const float* __restrict__ pos,
                            const float* __restrict__ cells,
                            const int* __restrict__ numbers,
                            const int* __restrict__ ei,
                            const int* __restrict__ eoff,
                            const int* __restrict__ batch) {
    int e = blockIdx.x * blockDim.x + threadIdx.x;
    if (e >= N_EDGES) return;
    int i = ei[e];
    int j = ei[N_EDGES + e];

    float pix = pos[3*i+0], piy = pos[3*i+1], piz = pos[3*i+2];
    float pjx = pos[3*j+0], pjy = pos[3*j+1], pjz = pos[3*j+2];

    int o0 = eoff[3*e+0], o1 = eoff[3*e+1], o2 = eoff[3*e+2];
    float sx = 0.f, sy = 0.f, sz = 0.f;
    if (o0 | o1 | o2) {
        int b = batch[i];
        const float* cb = cells + (size_t)b * 9;
        float f0 = (float)o0, f1 = (float)o1, f2 = (float)o2;
        sx = f0*cb[0] + f1*cb[3] + f2*cb[6];
        sy = f0*cb[1] + f1*cb[4] + f2*cb[7];
        sz = f0*cb[2] + f1*cb[5] + f2*cb[8];
    }

    float dx = pjx - pix + sx;
    float dy = pjy - piy + sy;
    float dz = pjz - piz + sz;
    float r2 = dx*dx + dy*dy + dz*dz + EPSR;
    float r  = sqrtf(r2);
    if (r >= CUTOFF) return;

    float inv = 1.0f / r;
    float a_c = r * (1.0f / CUTOFF);
    float fc  = 0.5f * (cospif(a_c) + 1.0f);
    float x = dx * inv, y = dy * inv, z = dz * inv;
    float x2 = x*x, y2 = y*y, z2 = z*z;

    float Y[16];
    Y[0]  = 0.28209479177387814f;
    Y[1]  = 0.4886025119029199f * y;
    Y[2]  = 0.4886025119029199f * z;
    Y[3]  = 0.4886025119029199f * x;
    Y[4]  = 1.0925484305920792f * x * y;
    Y[5]  = 1.0925484305920792f * y * z;
    Y[6]  = 0.31539156525252005f * (3.0f*z2 - 1.0f);
    Y[7]  = 1.0925484305920792f * x * z;
    Y[8]  = 0.5462742152960396f * (x2 - y2);
    Y[9]  = 0.5900435899266435f * y * (3.0f*x2 - y2);
    Y[10] = 2.890611442640554f  * x * y * z;
    Y[11] = 0.4570457994644658f * y * (5.0f*z2 - 1.0f);
    Y[12] = 0.3731763325901154f * z * (5.0f*z2 - 3.0f);
    Y[13] = 0.4570457994644658f * x * (5.0f*z2 - 1.0f);
    Y[14] = 1.445305721320277f  * z * (x2 - y2);
    Y[15] = 0.5900435899266435f * x * (x2 - 3.0f*y2);

    float rn[N_RADIAL];
    float scale = inv * fc;
    #pragma unroll
    for (int n = 0; n < N_RADIAL; n++)
        rn[n] = sinpif((float)(n + 1) * a_c) * scale;

    int sj = numbers[j];
    float* base = g_c + ((size_t)i * N_SPECIES + sj) * (N_RADIAL * N_SPH);

    #pragma unroll
    for (int n = 0; n < N_RADIAL; n++) {
        float rv = rn[n];
        #pragma unroll
        for (int m4 = 0; m4 < 4; m4++) {
            red4(base + n*16 + m4*4,
                 rv * Y[m4*4 + 0], rv * Y[m4*4 + 1],
                 rv * Y[m4*4 + 2], rv * Y[m4*4 + 3]);
        }
    }
}

// ---------------- K5: power spectrum (R12 proven version) ----------------
__global__ void ps_kernel() {
    __shared__ float cs[N_SPH][Q_DIM + 1];
    __shared__ int   pq[NPAIR];
    __shared__ int   pp[NPAIR];
    int a = blockIdx.x;
    int t = threadIdx.x;      // 128
    {
        const float4* ca = reinterpret_cast<const float4*>(g_c + (size_t)a * C_PER_ATOM);
        float4 v = ca[t];
        int q = t >> 2;
        int m = (t & 3) * 4;
        cs[m + 0][q] = v.x;
        cs[m + 1][q] = v.y;
        cs[m + 2][q] = v.z;
        cs[m + 3][q] = v.w;
    }
    for (int i = t; i < NPAIR; i += 128) {
        pq[i] = g_pairq[i];
        pp[i] = g_pairp[i];
    }
    __syncthreads();

    __nv_bfloat16* oh = g_psh + (size_t)a * PS_SYM;
    __nv_bfloat16* ol = g_psl + (size_t)a * PS_SYM;

    #pragma unroll
    for (int base = 0; base < NPAIR; base += 128) {
        int pr = base + t;
        if (pr >= NPAIR) break;
        int q = pq[pr], p = pp[pr];

        float s0, s1 = 0.f, s2 = 0.f, s3 = 0.f;
        s0 = cs[0][q] * cs[0][p];
        #pragma unroll
        for (int m = 1; m < 4; m++)  s1 += cs[m][q] * cs[m][p];
        #pragma unroll
        for (int m = 4; m < 9; m++)  s2 += cs[m][q] * cs[m][p];
        #pragma unroll
        for (int m = 9; m < 16; m++) s3 += cs[m][q] * cs[m][p];

        s1 *= 0.5773502691896258f;
        s2 *= 0.4472135954999579f;
        s3 *= 0.3779644730092272f;

        __nv_bfloat16 h0 = __float2bfloat16_rn(s0);
        __nv_bfloat16 h1 = __float2bfloat16_rn(s1);
        __nv_bfloat16 h2 = __float2bfloat16_rn(s2);
        __nv_bfloat16 h3 = __float2bfloat16_rn(s3);
        oh[pr]             = h0;
        oh[NPAIR + pr]     = h1;
        oh[2 * NPAIR + pr] = h2;
        oh[3 * NPAIR + pr] = h3;
        ol[pr]             = __float2bfloat16_rn(s0 - __bfloat162float(h0));
        ol[NPAIR + pr]     = __float2bfloat16_rn(s1 - __bfloat162float(h1));
        ol[2 * NPAIR + pr] = __float2bfloat16_rn(s2 - __bfloat162float(h2));
        ol[3 * NPAIR + pr] = __float2bfloat16_rn(s3 - __bfloat162float(h3));
    }
}

// ---------------- K6/K7: bf16x3 GEMM, 3-stage ring, fragment-reuse combo order ----------------
#define KPAD 72
#define STAGE_BF16 (128 * KPAD)
#define STAGE_BYTES (2 * STAGE_BF16 * 2)       // A+B per stage = 36864
#define GEMM_SMEM (3 * STAGE_BYTES)            // 110592 bytes

template<int WHICH>
__global__ void __launch_bounds__(256, 2) gemm_mma_kernel(
        const float* __restrict__ W3,
        const int* __restrict__ batch,
        float* __restrict__ out) {
    constexpr int K  = (WHICH == 1) ? PS_SYM : HID;
    constexpr int NS = K / 32;

    const int item  = blockIdx.x;
    const int tile  = item >> 1;
    const int nbase = (item & 1) * 128;

    int s = -1, mloc = 0, acc = 0;
    #pragma unroll
    for (int sp = 0; sp < N_SPECIES; sp++) {
        int ts = (g_counts[sp] + 127) >> 7;
        if (s < 0 && tile < acc + ts) { s = sp; mloc = (tile - acc) << 7; }
        acc += ts;
    }
    if (s < 0) return;
    const int row0   = g_off[s] + mloc;
    const int mcount = min(128, g_counts[s] - mloc);

    extern __shared__ __nv_bfloat16 smem[];
    __shared__ float w3s[128];
    __shared__ float srow[128];

    const int tid  = threadIdx.x;
    const int wid  = tid >> 5;
    const int lane = tid & 31;
    const int gid  = lane >> 2;
    const int tig  = lane & 3;
    const int wm   = wid & 1;
    const int wn   = wid >> 1;

    if (WHICH == 2) {
        if (tid < 128) {
            w3s[tid] = W3[s * HID + nbase + tid];
            srow[tid] = 0.f;
        }
    }

    const int lrow = tid >> 1;
    const int lh   = (tid & 1) * 16;
    const bool mvalid = (lrow < mcount);
    const int abytes = mvalid ? 16 : 0;
    const __nv_bfloat16* Ahrow = nullptr;
    const __nv_bfloat16* Alrow = nullptr;
    {
        int r = row0 + min(lrow, mcount - 1);
        int src = (WHICH == 1) ? g_sorted[r] : r;
        Ahrow = ((WHICH == 1) ? g_psh : g_h1h) + (size_t)src * K + lh;
        Alrow = ((WHICH == 1) ? g_psl : g_h1l) + (size_t)src * K + lh;
    }
    const __nv_bfloat16* Bhrow =
        ((WHICH == 1) ? g_w1h : g_w2h) + ((size_t)(s * HID + nbase + lrow)) * K + lh;
    const __nv_bfloat16* Blrow =
        ((WHICH == 1) ? g_w1l : g_w2l) + ((size_t)(s * HID + nbase + lrow)) * K + lh;

    const uint32_t smem_sh = (uint32_t)__cvta_generic_to_shared(smem);
    const uint32_t aDst = smem_sh + (lrow * KPAD + lh) * 2;
    const uint32_t bDst = smem_sh + (STAGE_BF16 + lrow * KPAD + lh) * 2;

    auto issue_stage = [&](int kt, int buf) {
        const uint32_t boff = (uint32_t)buf * STAGE_BYTES;
        const int kb = kt * 32;
        cp_async16(aDst + boff,           Ahrow + kb,     abytes);
        cp_async16(aDst + boff + 16,      Ahrow + kb + 8, abytes);
        cp_async16(aDst + boff + 64,      Alrow + kb,     abytes);
        cp_async16(aDst + boff + 64 + 16, Alrow + kb + 8, abytes);
        cp_async16(bDst + boff,           Bhrow + kb,     16);
        cp_async16(bDst + boff + 16,      Bhrow + kb + 8, 16);
        cp_async16(bDst + boff + 64,      Blrow + kb,     16);
        cp_async16(bDst + boff + 64 + 16, Blrow + kb + 8, 16);
        CP_COMMIT();
    };

    float accum[4][4][4];
    #pragma unroll
    for (int i = 0; i < 4; i++)
        #pragma unroll
        for (int j = 0; j < 4; j++)
            #pragma unroll
            for (int e = 0; e < 4; e++) accum[i][j][e] = 0.f;

    uint32_t aOff[4], bOff[2];
    #pragma unroll
    for (int mt = 0; mt < 4; mt++)
        aOff[mt] = (uint32_t)(((wm * 64 + mt * 16 + (lane & 15)) * KPAD
                               + (lane >> 4) * 8) * 2);
    #pragma unroll
    for (int ng = 0; ng < 2; ng++)
        bOff[ng] = (uint32_t)(((wn * 32 + ng * 16 + ((lane >> 4) << 3) + (lane & 7)) * KPAD
                               + ((lane >> 3) & 1) * 8) * 2);

    issue_stage(0, 0);
    if (NS > 1) issue_stage(1, 1);

    int buf = 0;
    for (int kt = 0; kt < NS; kt++) {
        if (kt + 1 < NS) { CP_WAIT(1); } else { CP_WAIT(0); }
        __syncthreads();
        if (kt + 2 < NS) issue_stage(kt + 2, (buf + 2) % 3);

        const uint32_t sA = smem_sh + (uint32_t)buf * STAGE_BYTES;
        const uint32_t sB = sA + STAGE_BF16 * 2;

        #pragma unroll
        for (int kk = 0; kk < 2; kk++) {
            const uint32_t k16 = kk * 16 * 2;
            const uint32_t klo = (32 + kk * 16) * 2;

            uint32_t ah[4][4];
            uint32_t bh0[4], bh1[4];
            ldmatrix_x4(bh0[0], bh0[1], bh0[2], bh0[3], sB + bOff[0] + k16);
            ldmatrix_x4(bh1[0], bh1[1], bh1[2], bh1[3], sB + bOff[1] + k16);
            #pragma unroll
            for (int mt = 0; mt < 4; mt++)
                ldmatrix_x4(ah[mt][0], ah[mt][1], ah[mt][2], ah[mt][3],
                            sA + aOff[mt] + k16);

            #pragma unroll
            for (int mt = 0; mt < 4; mt++) {
                mma_bf16(accum[mt][0][0], accum[mt][0][1], accum[mt][0][2], accum[mt][0][3],
                         ah[mt][0], ah[mt][1], ah[mt][2], ah[mt][3], bh0[0], bh0[1]);
                mma_bf16(accum[mt][1][0], accum[mt][1][1], accum[mt][1][2], accum[mt][1][3],
                         ah[mt][0], ah[mt][1], ah[mt][2], ah[mt][3], bh0[2], bh0[3]);
                mma_bf16(accum[mt][2][0], accum[mt][2][1], accum[mt][2][2], accum[mt][2][3],
                         ah[mt][0], ah[mt][1], ah[mt][2], ah[mt][3], bh1[0], bh1[1]);
                mma_bf16(accum[mt][3][0], accum[mt][3][1], accum[mt][3][2], accum[mt][3][3],
                         ah[mt][0], ah[mt][1], ah[mt][2], ah[mt][3], bh1[2], bh1[3]);
            }

            ldmatrix_x4(bh0[0], bh0[1], bh0[2], bh0[3], sB + bOff[0] + klo);
            ldmatrix_x4(bh1[0], bh1[1], bh1[2], bh1[3], sB + bOff[1] + klo);
            #pragma unroll
            for (int mt = 0; mt < 4; mt++) {
                mma_bf16(accum[mt][0][0], accum[mt][0][1], accum[mt][0][2], accum[mt][0][3],
                         ah[mt][0], ah[mt][1], ah[mt][2], ah[mt][3], bh0[0], bh0[1]);
                mma_bf16(accum[mt][1][0], accum[mt][1][1], accum[mt][1][2], accum[mt][1][3],
                         ah[mt][0], ah[mt][1], ah[mt][2], ah[mt][3], bh0[2], bh0[3]);
                mma_bf16(accum[mt][2][0], accum[mt][2][1], accum[mt][2][2], accum[mt][2][3],
                         ah[mt][0], ah[mt][1], ah[mt][2], ah[mt][3], bh1[0], bh1[1]);
                mma_bf16(accum[mt][3][0], accum[mt][3][1], accum[mt][3][2], accum[mt][3][3],
                         ah[mt][0], ah[mt][1], ah[mt][2], ah[mt][3], bh1[2], bh1[3]);
            }

            ldmatrix_x4(bh0[0], bh0[1], bh0[2], bh0[3], sB + bOff[0] + k16);
            ldmatrix_x4(bh1[0], bh1[1], bh1[2], bh1[3], sB + bOff[1] + k16);
            #pragma unroll
            for (int mt = 0; mt < 4; mt++)
                ldmatrix_x4(ah[mt][0], ah[mt][1], ah[mt][2], ah[mt][3],
                            sA + aOff[mt] + klo);
            #pragma unroll
            for (int mt = 0; mt < 4; mt++) {
                mma_bf16(accum[mt][0][0], accum[mt][0][1], accum[mt][0][2], accum[mt][0][3],
                         ah[mt][0], ah[mt][1], ah[mt][2], ah[mt][3], bh0[0], bh0[1]);
                mma_bf16(accum[mt][1][0], accum[mt][1][1], accum[mt][1][2], accum[mt][1][3],
                         ah[mt][0], ah[mt][1], ah[mt][2], ah[mt][3], bh0[2], bh0[3]);
                mma_bf16(accum[mt][2][0], accum[mt][2][1], accum[mt][2][2], accum[mt][2][3],
                         ah[mt][0], ah[mt][1], ah[mt][2], ah[mt][3], bh1[0], bh1[1]);
                mma_bf16(accum[mt][3][0], accum[mt][3][1], accum[mt][3][2], accum[mt][3][3],
                         ah[mt][0], ah[mt][1], ah[mt][2], ah[mt][3], bh1[2], bh1[3]);
            }
        }
        buf = (buf + 1) % 3;
    }
    __syncthreads();

    if (WHICH == 1) {
        #pragma unroll
        for (int mt = 0; mt < 4; mt++) {
            int r0 = wm * 64 + mt * 16 + gid;
            int r1 = r0 + 8;
            #pragma unroll
            for (int nt = 0; nt < 4; nt++) {
                int col = nbase + wn * 32 + nt * 8 + 2 * tig;
                if (r0 < mcount) {
                    float v0 = silu(accum[mt][nt][0]);
                    float v1 = silu(accum[mt][nt][1]);
                    __nv_bfloat16 h0 = __float2bfloat16_rn(v0);
                    __nv_bfloat16 h1 = __float2bfloat16_rn(v1);
                    size_t o = (size_t)(row0 + r0) * HID + col;
                    *reinterpret_cast<uint32_t*>(&g_h1h[o]) = pack2(h0, h1);
                    *reinterpret_cast<uint32_t*>(&g_h1l[o]) =
                        pack2(__float2bfloat16_rn(v0 - __bfloat162float(h0)),
                              __float2bfloat16_rn(v1 - __bfloat162float(h1)));
                }
                if (r1 < mcount) {
                    float v0 = silu(accum[mt][nt][2]);
                    float v1 = silu(accum[mt][nt][3]);
                    __nv_bfloat16 h0 = __float2bfloat16_rn(v0);
                    __nv_bfloat16 h1 = __float2bfloat16_rn(v1);
                    size_t o = (size_t)(row0 + r1) * HID + col;
                    *reinterpret_cast<uint32_t*>(&g_h1h[o]) = pack2(h0, h1);
                    *reinterpret_cast<uint32_t*>(&g_h1l[o]) =
                        pack2(__float2bfloat16_rn(v0 - __bfloat162float(h0)),
                              __float2bfloat16_rn(v1 - __bfloat162float(h1)));
                }
            }
        }
    } else {
        #pragma unroll
        for (int mt = 0; mt < 4; mt++) {
            int r0 = wm * 64 + mt * 16 + gid;
            float p0 = 0.f, p1 = 0.f;
            #pragma unroll
            for (int nt = 0; nt < 4; nt++) {
                int col = wn * 32 + nt * 8 + 2 * tig;
                float wa = w3s[col], wb = w3s[col + 1];
                p0 += silu(accum[mt][nt][0]) * wa + silu(accum[mt][nt][1]) * wb;
                p1 += silu(accum[mt][nt][2]) * wa + silu(accum[mt][nt][3]) * wb;
            }
            #pragma unroll
            for (int o = 1; o < 4; o <<= 1) {
                p0 += __shfl_xor_sync(0xFFFFFFFFu, p0, o);
                p1 += __shfl_xor_sync(0xFFFFFFFFu, p1, o);
            }
            if (tig == 0) {
                atomicAdd(&srow[r0], p0);
                atomicAdd(&srow[r0 + 8], p1);
            }
        }
        __syncthreads();
        if (tid < 128 && tid < mcount) {
            int a = g_sorted[row0 + tid];
            atomicAdd(&out[batch[a]], srow[tid]);
        }
    }
}

// ---------------- launch ----------------
extern "C" void kernel_launch(void* const* d_in, const int* in_sizes, int n_in,
                              void* d_out, int out_size) {
    const float* positions    = (const float*)d_in[0];
    const float* cells        = (const float*)d_in[1];
    const int*   numbers      = (const int*)  d_in[2];
    const int*   edge_indices = (const int*)  d_in[3];
    const int*   edge_offsets = (const int*)  d_in[4];
    const int*   batch        = (const int*)  d_in[5];
    const float* Wc           = (const float*)d_in[6];
    const float* W1           = (const float*)d_in[7];
    const float* W2           = (const float*)d_in[8];
    const float* W3           = (const float*)d_in[9];
    float* out = (float*)d_out;

    cudaFuncSetAttribute(gemm_mma_kernel<1>,
                         cudaFuncAttributeMaxDynamicSharedMemorySize, GEMM_SMEM);
    cudaFuncSetAttribute(gemm_mma_kernel<2>,
                         cudaFuncAttributeMaxDynamicSharedMemorySize, GEMM_SMEM);

    // PROFILING ROUND: sacrificial gemm1 launch at slot #4 (ncu captures launch #4).
    // It reads previous-replay state (valid & deterministic); outputs fully
    // overwritten by the real gemm1 below. g_counts is NOT re-zeroed until after
    // slot #4 so the sacrificial launch sees last replay's valid counts.
    zero_kernel<<<10000, 256>>>(out);                               // 1 (also pair table)
    edge_kernel<<<N_EDGES / 256, 256>>>(positions, cells, numbers,
                                        edge_indices, edge_offsets, batch);  // 2
    ps_kernel<<<N_ATOMS, 128>>>();                                  // 3
    gemm_mma_kernel<1><<<296, 256, GEMM_SMEM>>>(W3, batch, out);    // 4 (SACRIFICIAL)
    zero_counts_kernel<<<1, 32>>>();                                // 5
    atom_prep_kernel<<<(N_ATOMS + 255) / 256, 256>>>(numbers, batch, Wc, out); // 6
    offsets_kernel<<<1, 32>>>();                                    // 7
    scatter_kernel<<<(N_ATOMS + 255) / 256, 256>>>(numbers);        // 8
    fold_w1_kernel<<<dim3(66, 8, 4), dim3(32, 32)>>>(W1);           // 9
    fold_w2_kernel<<<dim3(8, 8, 4), dim3(32, 32)>>>(W2);            // 10
    gemm_mma_kernel<1><<<MAX_TILES * 2, 256, GEMM_SMEM>>>(W3, batch, out);    // 11 (real)
    gemm_mma_kernel<2><<<MAX_TILES * 2, 256, GEMM_SMEM>>>(W3, batch, out);    // 12
}

// round 16
// speedup vs baseline: 1.3670x; 1.3670x over previous
#include <cuda_runtime.h>
#include <cuda_bf16.h>
#include <math.h>
#include <stdint.h>

// ---------------- problem constants ----------------
#define N_ATOMS   20000
#define N_EDGES   640000
#define N_STRUCT  100
#define N_SPECIES 4
#define N_RADIAL  8
#define N_SPH     16
#define Q_DIM     32
#define C_PER_ATOM 512
#define PS_DIM    4096
#define NPAIR     528
#define PS_SYM    2112              // 66 * 32
#define HID       256
#define CUTOFF    5.0f
#define EPSR      1e-12f
#define MAX_TILES 160

// ---------------- scratch ----------------
__device__ float g_c  [(size_t)N_ATOMS * C_PER_ATOM];
__device__ float g_part[(size_t)N_ATOMS * HID];              // split-K partials
__device__ __nv_bfloat16 g_psh[(size_t)N_ATOMS * PS_SYM];
__device__ __nv_bfloat16 g_psl[(size_t)N_ATOMS * PS_SYM];
__device__ __nv_bfloat16 g_h1h[(size_t)N_ATOMS * HID];
__device__ __nv_bfloat16 g_h1l[(size_t)N_ATOMS * HID];
__device__ __nv_bfloat16 g_w1h[(size_t)N_SPECIES * HID * PS_SYM];
__device__ __nv_bfloat16 g_w1l[(size_t)N_SPECIES * HID * PS_SYM];
__device__ __nv_bfloat16 g_w2h[(size_t)N_SPECIES * HID * HID];
__device__ __nv_bfloat16 g_w2l[(size_t)N_SPECIES * HID * HID];
__device__ int   g_pairq[NPAIR];
__device__ int   g_pairp[NPAIR];
__device__ int   g_counts[N_SPECIES];
__device__ int   g_off[N_SPECIES];
__device__ int   g_cursor[N_SPECIES];
__device__ int   g_sorted[N_ATOMS];

// ---------------- helpers ----------------
__device__ __forceinline__ float silu(float x) { return x / (1.0f + expf(-x)); }

__device__ __forceinline__ void red4(float* p, float a, float b, float c, float d) {
    asm volatile("red.global.add.v4.f32 [%0], {%1,%2,%3,%4};"
                 :: "l"(p), "f"(a), "f"(b), "f"(c), "f"(d) : "memory");
}

__device__ __forceinline__ uint32_t pack2(__nv_bfloat16 a, __nv_bfloat16 b) {
    return (uint32_t)__bfloat16_as_ushort(a) | ((uint32_t)__bfloat16_as_ushort(b) << 16);
}

__device__ __forceinline__ void mma_bf16(float& c0, float& c1, float& c2, float& c3,
                                         uint32_t a0, uint32_t a1, uint32_t a2, uint32_t a3,
                                         uint32_t b0, uint32_t b1) {
    asm volatile("mma.sync.aligned.m16n8k16.row.col.f32.bf16.bf16.f32 "
                 "{%0,%1,%2,%3}, {%4,%5,%6,%7}, {%8,%9}, {%0,%1,%2,%3};"
                 : "+f"(c0), "+f"(c1), "+f"(c2), "+f"(c3)
                 : "r"(a0), "r"(a1), "r"(a2), "r"(a3), "r"(b0), "r"(b1));
}

__device__ __forceinline__ void ldmatrix_x4(uint32_t& r0, uint32_t& r1,
                                            uint32_t& r2, uint32_t& r3, uint32_t addr) {
    asm volatile("ldmatrix.sync.aligned.m8n8.x4.shared.b16 {%0,%1,%2,%3}, [%4];"
                 : "=r"(r0), "=r"(r1), "=r"(r2), "=r"(r3) : "r"(addr));
}

__device__ __forceinline__ void cp_async16(uint32_t dst, const void* src, int src_bytes) {
    asm volatile("cp.async.cg.shared.global [%0], [%1], 16, %2;"
                 :: "r"(dst), "l"(src), "r"(src_bytes) : "memory");
}
#define CP_COMMIT() asm volatile("cp.async.commit_group;" ::: "memory")
#define CP_WAIT(n)  asm volatile("cp.async.wait_group %0;" :: "n"(n) : "memory")

// ---------------- K0: zero g_c + out + counts, build pair table (block 0) ----------------
__global__ void zero_kernel(float* __restrict__ out) {
    size_t idx = (size_t)blockIdx.x * blockDim.x + threadIdx.x;
    float4* c4 = reinterpret_cast<float4*>(g_c);
    c4[idx] = make_float4(0.f, 0.f, 0.f, 0.f);
    if (idx < N_STRUCT) out[idx] = 0.f;
    if (idx < N_SPECIES) g_counts[idx] = 0;
    if (blockIdx.x == 0) {
        for (int i = threadIdx.x; i < NPAIR; i += blockDim.x) {
            int q = 0, off = 0;
            while (off + (Q_DIM - q) <= i) { off += Q_DIM - q; q++; }
            g_pairq[i] = q;
            g_pairp[i] = q + (i - off);
        }
    }
}

// ---------------- K1 ----------------
__global__ void atom_prep_kernel(const int* __restrict__ numbers,
                                 const int* __restrict__ batch,
                                 const float* __restrict__ Wc,
                                 float* __restrict__ out) {
    int a = blockIdx.x * blockDim.x + threadIdx.x;
    if (a >= N_ATOMS) return;
    int s = numbers[a];
    atomicAdd(&g_counts[s], 1);
    atomicAdd(&out[batch[a]], Wc[s]);
}

// ---------------- K2: scan only ----------------
__global__ void offsets_kernel() {
    if (threadIdx.x == 0) {
        int acc = 0;
        for (int s = 0; s < N_SPECIES; s++) {
            g_off[s] = acc;
            g_cursor[s] = acc;
            acc += g_counts[s];
        }
    }
}

// ---------------- K3 ----------------
__global__ void scatter_kernel(const int* __restrict__ numbers) {
    int a = blockIdx.x * blockDim.x + threadIdx.x;
    if (a >= N_ATOMS) return;
    int s = numbers[a];
    int pos = atomicAdd(&g_cursor[s], 1);
    g_sorted[pos] = a;
}

// ---------------- K3b: fold W1 + transpose + split ----------------
__global__ void fold_w1_kernel(const float* __restrict__ W1) {
    __shared__ float tile[32][33];
    int tx = threadIdx.x, ty = threadIdx.y;
    int k = blockIdx.x * 32 + ty;
    int n = blockIdx.y * 32 + tx;
    int l  = k / NPAIR;
    int pr = k - l * NPAIR;
    int q = g_pairq[pr], p = g_pairp[pr];
    const float* Ws = W1 + (size_t)blockIdx.z * PS_DIM * HID;
    float v = Ws[(size_t)(l * 1024 + q * 32 + p) * HID + n];
    if (q != p)
        v += Ws[(size_t)(l * 1024 + p * 32 + q) * HID + n];
    tile[ty][tx] = v;
    __syncthreads();
    int nn = blockIdx.y * 32 + ty;
    int kk = blockIdx.x * 32 + tx;
    float w = tile[tx][ty];
    __nv_bfloat16 h = __float2bfloat16_rn(w);
    size_t oi = ((size_t)(blockIdx.z * HID + nn)) * PS_SYM + kk;
    g_w1h[oi] = h;
    g_w1l[oi] = __float2bfloat16_rn(w - __bfloat162float(h));
}

// ---------------- K3c: W2 transpose + split ----------------
__global__ void fold_w2_kernel(const float* __restrict__ W2) {
    __shared__ float tile[32][33];
    int tx = threadIdx.x, ty = threadIdx.y;
    int k = blockIdx.x * 32 + ty;
    int n = blockIdx.y * 32 + tx;
    tile[ty][tx] = W2[((size_t)(blockIdx.z * HID + k)) * HID + n];
    __syncthreads();
    int nn = blockIdx.y * 32 + ty;
    int kk = blockIdx.x * 32 + tx;
    float w = tile[tx][ty];
    __nv_bfloat16 h = __float2bfloat16_rn(w);
    size_t oi = ((size_t)(blockIdx.z * HID + nn)) * HID + kk;
    g_w2h[oi] = h;
    g_w2l[oi] = __float2bfloat16_rn(w - __bfloat162float(h));
}

// ---------------- K4: edge featurization ----------------
__global__ void edge_kernel(const float* __restrict__ pos,
                            const float* __restrict__ cells,
                            const int* __restrict__ numbers,
                            const int* __restrict__ ei,
                            const int* __restrict__ eoff,
                            const int* __restrict__ batch) {
    int e = blockIdx.x * blockDim.x + threadIdx.x;
    if (e >= N_EDGES) return;
    int i = ei[e];
    int j = ei[N_EDGES + e];

    float pix = pos[3*i+0], piy = pos[3*i+1], piz = pos[3*i+2];
    float pjx = pos[3*j+0], pjy = pos[3*j+1], pjz = pos[3*j+2];

    int o0 = eoff[3*e+0], o1 = eoff[3*e+1], o2 = eoff[3*e+2];
    float sx = 0.f, sy = 0.f, sz = 0.f;
    if (o0 | o1 | o2) {
        int b = batch[i];
        const float* cb = cells + (size_t)b * 9;
        float f0 = (float)o0, f1 = (float)o1, f2 = (float)o2;
        sx = f0*cb[0] + f1*cb[3] + f2*cb[6];
        sy = f0*cb[1] + f1*cb[4] + f2*cb[7];
        sz = f0*cb[2] + f1*cb[5] + f2*cb[8];
    }

    float dx = pjx - pix + sx;
    float dy = pjy - piy + sy;
    float dz = pjz - piz + sz;
    float r2 = dx*dx + dy*dy + dz*dz + EPSR;
    float r  = sqrtf(r2);
    if (r >= CUTOFF) return;

    float inv = 1.0f / r;
    float a_c = r * (1.0f / CUTOFF);
    float fc  = 0.5f * (cospif(a_c) + 1.0f);
    float x = dx * inv, y = dy * inv, z = dz * inv;
    float x2 = x*x, y2 = y*y, z2 = z*z;

    float Y[16];
    Y[0]  = 0.28209479177387814f;
    Y[1]  = 0.4886025119029199f * y;
    Y[2]  = 0.4886025119029199f * z;
    Y[3]  = 0.4886025119029199f * x;
    Y[4]  = 1.0925484305920792f * x * y;
    Y[5]  = 1.0925484305920792f * y * z;
    Y[6]  = 0.31539156525252005f * (3.0f*z2 - 1.0f);
    Y[7]  = 1.0925484305920792f * x * z;
    Y[8]  = 0.5462742152960396f * (x2 - y2);
    Y[9]  = 0.5900435899266435f * y * (3.0f*x2 - y2);
    Y[10] = 2.890611442640554f  * x * y * z;
    Y[11] = 0.4570457994644658f * y * (5.0f*z2 - 1.0f);
    Y[12] = 0.3731763325901154f * z * (5.0f*z2 - 3.0f);
    Y[13] = 0.4570457994644658f * x * (5.0f*z2 - 1.0f);
    Y[14] = 1.445305721320277f  * z * (x2 - y2);
    Y[15] = 0.5900435899266435f * x * (x2 - 3.0f*y2);

    float rn[N_RADIAL];
    float scale = inv * fc;
    #pragma unroll
    for (int n = 0; n < N_RADIAL; n++)
        rn[n] = sinpif((float)(n + 1) * a_c) * scale;

    int sj = numbers[j];
    float* base = g_c + ((size_t)i * N_SPECIES + sj) * (N_RADIAL * N_SPH);

    #pragma unroll
    for (int n = 0; n < N_RADIAL; n++) {
        float rv = rn[n];
        #pragma unroll
        for (int m4 = 0; m4 < 4; m4++) {
            red4(base + n*16 + m4*4,
                 rv * Y[m4*4 + 0], rv * Y[m4*4 + 1],
                 rv * Y[m4*4 + 2], rv * Y[m4*4 + 3]);
        }
    }
}

// ---------------- K5: power spectrum (R12 proven version) ----------------
__global__ void ps_kernel() {
    __shared__ float cs[N_SPH][Q_DIM + 1];
    __shared__ int   pq[NPAIR];
    __shared__ int   pp[NPAIR];
    int a = blockIdx.x;
    int t = threadIdx.x;      // 128
    {
        const float4* ca = reinterpret_cast<const float4*>(g_c + (size_t)a * C_PER_ATOM);
        float4 v = ca[t];
        int q = t >> 2;
        int m = (t & 3) * 4;
        cs[m + 0][q] = v.x;
        cs[m + 1][q] = v.y;
        cs[m + 2][q] = v.z;
        cs[m + 3][q] = v.w;
    }
    for (int i = t; i < NPAIR; i += 128) {
        pq[i] = g_pairq[i];
        pp[i] = g_pairp[i];
    }
    __syncthreads();

    __nv_bfloat16* oh = g_psh + (size_t)a * PS_SYM;
    __nv_bfloat16* ol = g_psl + (size_t)a * PS_SYM;

    #pragma unroll
    for (int base = 0; base < NPAIR; base += 128) {
        int pr = base + t;
        if (pr >= NPAIR) break;
        int q = pq[pr], p = pp[pr];

        float s0, s1 = 0.f, s2 = 0.f, s3 = 0.f;
        s0 = cs[0][q] * cs[0][p];
        #pragma unroll
        for (int m = 1; m < 4; m++)  s1 += cs[m][q] * cs[m][p];
        #pragma unroll
        for (int m = 4; m < 9; m++)  s2 += cs[m][q] * cs[m][p];
        #pragma unroll
        for (int m = 9; m < 16; m++) s3 += cs[m][q] * cs[m][p];

        s1 *= 0.5773502691896258f;
        s2 *= 0.4472135954999579f;
        s3 *= 0.3779644730092272f;

        __nv_bfloat16 h0 = __float2bfloat16_rn(s0);
        __nv_bfloat16 h1 = __float2bfloat16_rn(s1);
        __nv_bfloat16 h2 = __float2bfloat16_rn(s2);
        __nv_bfloat16 h3 = __float2bfloat16_rn(s3);
        oh[pr]             = h0;
        oh[NPAIR + pr]     = h1;
        oh[2 * NPAIR + pr] = h2;
        oh[3 * NPAIR + pr] = h3;
        ol[pr]             = __float2bfloat16_rn(s0 - __bfloat162float(h0));
        ol[NPAIR + pr]     = __float2bfloat16_rn(s1 - __bfloat162float(h1));
        ol[2 * NPAIR + pr] = __float2bfloat16_rn(s2 - __bfloat162float(h2));
        ol[3 * NPAIR + pr] = __float2bfloat16_rn(s3 - __bfloat162float(h3));
    }
}

// ---------------- K6: bf16x3 GEMM, 3-stage ring, split-K ----------------
// MODE 0: gemm1a — K stages [0,33), write raw fp32 partials to g_part.
// MODE 1: gemm1b — K stages [33,66), add g_part, silu, split-store h1h/h1l.
// MODE 2: gemm2  — K=256 (8 stages), fused W3 epilogue.
#define KPAD 72
#define STAGE_BF16 (128 * KPAD)
#define STAGE_BYTES (2 * STAGE_BF16 * 2)       // A+B per stage = 36864
#define GEMM_SMEM (3 * STAGE_BYTES)            // 110592 bytes

template<int MODE>
__global__ void __launch_bounds__(256, 2) gemm_mma_kernel(
        const float* __restrict__ W3,
        const int* __restrict__ batch,
        float* __restrict__ out) {
    constexpr int K     = (MODE == 2) ? HID : PS_SYM;
    constexpr int NS    = (MODE == 2) ? 8 : 33;
    constexpr int KBASE = (MODE == 1) ? 33 * 32 : 0;

    const int item  = blockIdx.x;
    const int tile  = item >> 1;
    const int nbase = (item & 1) * 128;

    int s = -1, mloc = 0, acc = 0;
    #pragma unroll
    for (int sp = 0; sp < N_SPECIES; sp++) {
        int ts = (g_counts[sp] + 127) >> 7;
        if (s < 0 && tile < acc + ts) { s = sp; mloc = (tile - acc) << 7; }
        acc += ts;
    }
    if (s < 0) return;
    const int row0   = g_off[s] + mloc;
    const int mcount = min(128, g_counts[s] - mloc);

    extern __shared__ __nv_bfloat16 smem[];
    __shared__ float w3s[128];
    __shared__ float srow[128];

    const int tid  = threadIdx.x;
    const int wid  = tid >> 5;
    const int lane = tid & 31;
    const int gid  = lane >> 2;
    const int tig  = lane & 3;
    const int wm   = wid & 1;
    const int wn   = wid >> 1;

    if (MODE == 2) {
        if (tid < 128) {
            w3s[tid] = W3[s * HID + nbase + tid];
            srow[tid] = 0.f;
        }
    }

    const int lrow = tid >> 1;
    const int lh   = (tid & 1) * 16;
    const bool mvalid = (lrow < mcount);
    const int abytes = mvalid ? 16 : 0;
    const __nv_bfloat16* Ahrow = nullptr;
    const __nv_bfloat16* Alrow = nullptr;
    {
        int r = row0 + min(lrow, mcount - 1);
        int src = (MODE == 2) ? r : g_sorted[r];
        Ahrow = ((MODE == 2) ? g_h1h : g_psh) + (size_t)src * K + lh;
        Alrow = ((MODE == 2) ? g_h1l : g_psl) + (size_t)src * K + lh;
    }
    const __nv_bfloat16* Bhrow =
        ((MODE == 2) ? g_w2h : g_w1h) + ((size_t)(s * HID + nbase + lrow)) * K + lh;
    const __nv_bfloat16* Blrow =
        ((MODE == 2) ? g_w2l : g_w1l) + ((size_t)(s * HID + nbase + lrow)) * K + lh;

    const uint32_t smem_sh = (uint32_t)__cvta_generic_to_shared(smem);
    const uint32_t aDst = smem_sh + (lrow * KPAD + lh) * 2;
    const uint32_t bDst = smem_sh + (STAGE_BF16 + lrow * KPAD + lh) * 2;

    auto issue_stage = [&](int kt, int buf) {
        const uint32_t boff = (uint32_t)buf * STAGE_BYTES;
        const int kb = KBASE + kt * 32;
        cp_async16(aDst + boff,           Ahrow + kb,     abytes);
        cp_async16(aDst + boff + 16,      Ahrow + kb + 8, abytes);
        cp_async16(aDst + boff + 64,      Alrow + kb,     abytes);
        cp_async16(aDst + boff + 64 + 16, Alrow + kb + 8, abytes);
        cp_async16(bDst + boff,           Bhrow + kb,     16);
        cp_async16(bDst + boff + 16,      Bhrow + kb + 8, 16);
        cp_async16(bDst + boff + 64,      Blrow + kb,     16);
        cp_async16(bDst + boff + 64 + 16, Blrow + kb + 8, 16);
        CP_COMMIT();
    };

    float accum[4][4][4];
    #pragma unroll
    for (int i = 0; i < 4; i++)
        #pragma unroll
        for (int j = 0; j < 4; j++)
            #pragma unroll
            for (int e = 0; e < 4; e++) accum[i][j][e] = 0.f;

    uint32_t aOff[4], bOff[2];
    #pragma unroll
    for (int mt = 0; mt < 4; mt++)
        aOff[mt] = (uint32_t)(((wm * 64 + mt * 16 + (lane & 15)) * KPAD
                               + (lane >> 4) * 8) * 2);
    #pragma unroll
    for (int ng = 0; ng < 2; ng++)
        bOff[ng] = (uint32_t)(((wn * 32 + ng * 16 + ((lane >> 4) << 3) + (lane & 7)) * KPAD
                               + ((lane >> 3) & 1) * 8) * 2);

    issue_stage(0, 0);
    if (NS > 1) issue_stage(1, 1);

    int buf = 0;
    for (int kt = 0; kt < NS; kt++) {
        if (kt + 1 < NS) { CP_WAIT(1); } else { CP_WAIT(0); }
        __syncthreads();
        if (kt + 2 < NS) issue_stage(kt + 2, (buf + 2) % 3);

        const uint32_t sA = smem_sh + (uint32_t)buf * STAGE_BYTES;
        const uint32_t sB = sA + STAGE_BF16 * 2;

        #pragma unroll
        for (int kk = 0; kk < 2; kk++) {
            const uint32_t k16 = kk * 16 * 2;
            const uint32_t klo = (32 + kk * 16) * 2;

            uint32_t ah[4][4];
            uint32_t bh0[4], bh1[4];
            ldmatrix_x4(bh0[0], bh0[1], bh0[2], bh0[3], sB + bOff[0] + k16);
            ldmatrix_x4(bh1[0], bh1[1], bh1[2], bh1[3], sB + bOff[1] + k16);
            #pragma unroll
            for (int mt = 0; mt < 4; mt++)
                ldmatrix_x4(ah[mt][0], ah[mt][1], ah[mt][2], ah[mt][3],
                            sA + aOff[mt] + k16);

            #pragma unroll
            for (int mt = 0; mt < 4; mt++) {
                mma_bf16(accum[mt][0][0], accum[mt][0][1], accum[mt][0][2], accum[mt][0][3],
                         ah[mt][0], ah[mt][1], ah[mt][2], ah[mt][3], bh0[0], bh0[1]);
                mma_bf16(accum[mt][1][0], accum[mt][1][1], accum[mt][1][2], accum[mt][1][3],
                         ah[mt][0], ah[mt][1], ah[mt][2], ah[mt][3], bh0[2], bh0[3]);
                mma_bf16(accum[mt][2][0], accum[mt][2][1], accum[mt][2][2], accum[mt][2][3],
                         ah[mt][0], ah[mt][1], ah[mt][2], ah[mt][3], bh1[0], bh1[1]);
                mma_bf16(accum[mt][3][0], accum[mt][3][1], accum[mt][3][2], accum[mt][3][3],
                         ah[mt][0], ah[mt][1], ah[mt][2], ah[mt][3], bh1[2], bh1[3]);
            }

            ldmatrix_x4(bh0[0], bh0[1], bh0[2], bh0[3], sB + bOff[0] + klo);
            ldmatrix_x4(bh1[0], bh1[1], bh1[2], bh1[3], sB + bOff[1] + klo);
            #pragma unroll
            for (int mt = 0; mt < 4; mt++) {
                mma_bf16(accum[mt][0][0], accum[mt][0][1], accum[mt][0][2], accum[mt][0][3],
                         ah[mt][0], ah[mt][1], ah[mt][2], ah[mt][3], bh0[0], bh0[1]);
                mma_bf16(accum[mt][1][0], accum[mt][1][1], accum[mt][1][2], accum[mt][1][3],
                         ah[mt][0], ah[mt][1], ah[mt][2], ah[mt][3], bh0[2], bh0[3]);
                mma_bf16(accum[mt][2][0], accum[mt][2][1], accum[mt][2][2], accum[mt][2][3],
                         ah[mt][0], ah[mt][1], ah[mt][2], ah[mt][3], bh1[0], bh1[1]);
                mma_bf16(accum[mt][3][0], accum[mt][3][1], accum[mt][3][2], accum[mt][3][3],
                         ah[mt][0], ah[mt][1], ah[mt][2], ah[mt][3], bh1[2], bh1[3]);
            }

            ldmatrix_x4(bh0[0], bh0[1], bh0[2], bh0[3], sB + bOff[0] + k16);
            ldmatrix_x4(bh1[0], bh1[1], bh1[2], bh1[3], sB + bOff[1] + k16);
            #pragma unroll
            for (int mt = 0; mt < 4; mt++)
                ldmatrix_x4(ah[mt][0], ah[mt][1], ah[mt][2], ah[mt][3],
                            sA + aOff[mt] + klo);
            #pragma unroll
            for (int mt = 0; mt < 4; mt++) {
                mma_bf16(accum[mt][0][0], accum[mt][0][1], accum[mt][0][2], accum[mt][0][3],
                         ah[mt][0], ah[mt][1], ah[mt][2], ah[mt][3], bh0[0], bh0[1]);
                mma_bf16(accum[mt][1][0], accum[mt][1][1], accum[mt][1][2], accum[mt][1][3],
                         ah[mt][0], ah[mt][1], ah[mt][2], ah[mt][3], bh0[2], bh0[3]);
                mma_bf16(accum[mt][2][0], accum[mt][2][1], accum[mt][2][2], accum[mt][2][3],
                         ah[mt][0], ah[mt][1], ah[mt][2], ah[mt][3], bh1[0], bh1[1]);
                mma_bf16(accum[mt][3][0], accum[mt][3][1], accum[mt][3][2], accum[mt][3][3],
                         ah[mt][0], ah[mt][1], ah[mt][2], ah[mt][3], bh1[2], bh1[3]);
            }
        }
        buf = (buf + 1) % 3;
    }
    __syncthreads();

    if (MODE == 0) {
        // write raw fp32 partials
        #pragma unroll
        for (int mt = 0; mt < 4; mt++) {
            int r0 = wm * 64 + mt * 16 + gid;
            int r1 = r0 + 8;
            #pragma unroll
            for (int nt = 0; nt < 4; nt++) {
                int col = nbase + wn * 32 + nt * 8 + 2 * tig;
                if (r0 < mcount) {
                    float2 v; v.x = accum[mt][nt][0]; v.y = accum[mt][nt][1];
                    *reinterpret_cast<float2*>(&g_part[(size_t)(row0 + r0) * HID + col]) = v;
                }
                if (r1 < mcount) {
                    float2 v; v.x = accum[mt][nt][2]; v.y = accum[mt][nt][3];
                    *reinterpret_cast<float2*>(&g_part[(size_t)(row0 + r1) * HID + col]) = v;
                }
            }
        }
    } else if (MODE == 1) {
        // add partial, silu, split-store h1
        #pragma unroll
        for (int mt = 0; mt < 4; mt++) {
            int r0 = wm * 64 + mt * 16 + gid;
            int r1 = r0 + 8;
            #pragma unroll
            for (int nt = 0; nt < 4; nt++) {
                int col = nbase + wn * 32 + nt * 8 + 2 * tig;
                if (r0 < mcount) {
                    float2 pv = *reinterpret_cast<const float2*>(
                        &g_part[(size_t)(row0 + r0) * HID + col]);
                    float v0 = silu(accum[mt][nt][0] + pv.x);
                    float v1 = silu(accum[mt][nt][1] + pv.y);
                    __nv_bfloat16 h0 = __float2bfloat16_rn(v0);
                    __nv_bfloat16 h1 = __float2bfloat16_rn(v1);
                    size_t o = (size_t)(row0 + r0) * HID + col;
                    *reinterpret_cast<uint32_t*>(&g_h1h[o]) = pack2(h0, h1);
                    *reinterpret_cast<uint32_t*>(&g_h1l[o]) =
                        pack2(__float2bfloat16_rn(v0 - __bfloat162float(h0)),
                              __float2bfloat16_rn(v1 - __bfloat162float(h1)));
                }
                if (r1 < mcount) {
                    float2 pv = *reinterpret_cast<const float2*>(
                        &g_part[(size_t)(row0 + r1) * HID + col]);
                    float v0 = silu(accum[mt][nt][2] + pv.x);
                    float v1 = silu(accum[mt][nt][3] + pv.y);
                    __nv_bfloat16 h0 = __float2bfloat16_rn(v0);
                    __nv_bfloat16 h1 = __float2bfloat16_rn(v1);
                    size_t o = (size_t)(row0 + r1) * HID + col;
                    *reinterpret_cast<uint32_t*>(&g_h1h[o]) = pack2(h0, h1);
                    *reinterpret_cast<uint32_t*>(&g_h1l[o]) =
                        pack2(__float2bfloat16_rn(v0 - __bfloat162float(h0)),
                              __float2bfloat16_rn(v1 - __bfloat162float(h1)));
                }
            }
        }
    } else {
        // fused layer-3
        #pragma unroll
        for (int mt = 0; mt < 4; mt++) {
            int r0 = wm * 64 + mt * 16 + gid;
            float p0 = 0.f, p1 = 0.f;
            #pragma unroll
            for (int nt = 0; nt < 4; nt++) {
                int col = wn * 32 + nt * 8 + 2 * tig;
                float wa = w3s[col], wb = w3s[col + 1];
                p0 += silu(accum[mt][nt][0]) * wa + silu(accum[mt][nt][1]) * wb;
                p1 += silu(accum[mt][nt][2]) * wa + silu(accum[mt][nt][3]) * wb;
            }
            #pragma unroll
            for (int o = 1; o < 4; o <<= 1) {
                p0 += __shfl_xor_sync(0xFFFFFFFFu, p0, o);
                p1 += __shfl_xor_sync(0xFFFFFFFFu, p1, o);
            }
            if (tig == 0) {
                atomicAdd(&srow[r0], p0);
                atomicAdd(&srow[r0 + 8], p1);
            }
        }
        __syncthreads();
        if (tid < 128 && tid < mcount) {
            int a = g_sorted[row0 + tid];
            atomicAdd(&out[batch[a]], srow[tid]);
        }
    }
}

// ---------------- launch ----------------
extern "C" void kernel_launch(void* const* d_in, const int* in_sizes, int n_in,
                              void* d_out, int out_size) {
    const float* positions    = (const float*)d_in[0];
    const float* cells        = (const float*)d_in[1];
    const int*   numbers      = (const int*)  d_in[2];
    const int*   edge_indices = (const int*)  d_in[3];
    const int*   edge_offsets = (const int*)  d_in[4];
    const int*   batch        = (const int*)  d_in[5];
    const float* Wc           = (const float*)d_in[6];
    const float* W1           = (const float*)d_in[7];
    const float* W2           = (const float*)d_in[8];
    const float* W3           = (const float*)d_in[9];
    float* out = (float*)d_out;

    cudaFuncSetAttribute(gemm_mma_kernel<0>,
                         cudaFuncAttributeMaxDynamicSharedMemorySize, GEMM_SMEM);
    cudaFuncSetAttribute(gemm_mma_kernel<1>,
                         cudaFuncAttributeMaxDynamicSharedMemorySize, GEMM_SMEM);
    cudaFuncSetAttribute(gemm_mma_kernel<2>,
                         cudaFuncAttributeMaxDynamicSharedMemorySize, GEMM_SMEM);

    zero_kernel<<<10000, 256>>>(out);
    atom_prep_kernel<<<(N_ATOMS + 255) / 256, 256>>>(numbers, batch, Wc, out);
    offsets_kernel<<<1, 32>>>();
    edge_kernel<<<N_EDGES / 256, 256>>>(positions, cells, numbers,
                                        edge_indices, edge_offsets, batch);
    scatter_kernel<<<(N_ATOMS + 255) / 256, 256>>>(numbers);
    ps_kernel<<<N_ATOMS, 128>>>();
    fold_w1_kernel<<<dim3(66, 8, 4), dim3(32, 32)>>>(W1);
    fold_w2_kernel<<<dim3(8, 8, 4), dim3(32, 32)>>>(W2);
    gemm_mma_kernel<0><<<MAX_TILES * 2, 256, GEMM_SMEM>>>(W3, batch, out);
    gemm_mma_kernel<1><<<MAX_TILES * 2, 256, GEMM_SMEM>>>(W3, batch, out);
    gemm_mma_kernel<2><<<MAX_TILES * 2, 256, GEMM_SMEM>>>(W3, batch, out);
}

// round 17
// speedup vs baseline: 1.4324x; 1.0479x over previous
#include <cuda_runtime.h>
#include <cuda_bf16.h>
#include <math.h>
#include <stdint.h>

// ---------------- problem constants ----------------
#define N_ATOMS   20000
#define N_EDGES   640000
#define N_STRUCT  100
#define N_SPECIES 4
#define N_RADIAL  8
#define N_SPH     16
#define Q_DIM     32
#define C_PER_ATOM 512
#define PS_DIM    4096
#define NPAIR     528
#define PS_SYM    2112              // 528 pairs * 4 l-blocks (pair-major K layout)
#define HID       256
#define CUTOFF    5.0f
#define EPSR      1e-12f
#define MAX_TILES 160

// ---------------- scratch ----------------
__device__ float g_c  [(size_t)N_ATOMS * C_PER_ATOM];
__device__ __nv_bfloat16 g_psh[(size_t)N_ATOMS * PS_SYM];
__device__ __nv_bfloat16 g_psl[(size_t)N_ATOMS * PS_SYM];
__device__ __nv_bfloat16 g_h1h[(size_t)N_ATOMS * HID];
__device__ __nv_bfloat16 g_h1l[(size_t)N_ATOMS * HID];
__device__ __nv_bfloat16 g_w1h[(size_t)N_SPECIES * HID * PS_SYM];
__device__ __nv_bfloat16 g_w1l[(size_t)N_SPECIES * HID * PS_SYM];
__device__ __nv_bfloat16 g_w2h[(size_t)N_SPECIES * HID * HID];
__device__ __nv_bfloat16 g_w2l[(size_t)N_SPECIES * HID * HID];
__device__ int   g_pairq[NPAIR];
__device__ int   g_pairp[NPAIR];
__device__ int   g_counts[N_SPECIES];
__device__ int   g_off[N_SPECIES];
__device__ int   g_cursor[N_SPECIES];
__device__ int   g_sorted[N_ATOMS];

// ---------------- helpers ----------------
__device__ __forceinline__ float silu(float x) { return x / (1.0f + expf(-x)); }

__device__ __forceinline__ void red4(float* p, float a, float b, float c, float d) {
    asm volatile("red.global.add.v4.f32 [%0], {%1,%2,%3,%4};"
                 :: "l"(p), "f"(a), "f"(b), "f"(c), "f"(d) : "memory");
}

__device__ __forceinline__ uint32_t pack2(__nv_bfloat16 a, __nv_bfloat16 b) {
    return (uint32_t)__bfloat16_as_ushort(a) | ((uint32_t)__bfloat16_as_ushort(b) << 16);
}

__device__ __forceinline__ uint64_t pack4(__nv_bfloat16 a, __nv_bfloat16 b,
                                          __nv_bfloat16 c, __nv_bfloat16 d) {
    return (uint64_t)__bfloat16_as_ushort(a)
         | ((uint64_t)__bfloat16_as_ushort(b) << 16)
         | ((uint64_t)__bfloat16_as_ushort(c) << 32)
         | ((uint64_t)__bfloat16_as_ushort(d) << 48);
}

__device__ __forceinline__ void mma_bf16(float& c0, float& c1, float& c2, float& c3,
                                         uint32_t a0, uint32_t a1, uint32_t a2, uint32_t a3,
                                         uint32_t b0, uint32_t b1) {
    asm volatile("mma.sync.aligned.m16n8k16.row.col.f32.bf16.bf16.f32 "
                 "{%0,%1,%2,%3}, {%4,%5,%6,%7}, {%8,%9}, {%0,%1,%2,%3};"
                 : "+f"(c0), "+f"(c1), "+f"(c2), "+f"(c3)
                 : "r"(a0), "r"(a1), "r"(a2), "r"(a3), "r"(b0), "r"(b1));
}

__device__ __forceinline__ void ldmatrix_x4(uint32_t& r0, uint32_t& r1,
                                            uint32_t& r2, uint32_t& r3, uint32_t addr) {
    asm volatile("ldmatrix.sync.aligned.m8n8.x4.shared.b16 {%0,%1,%2,%3}, [%4];"
                 : "=r"(r0), "=r"(r1), "=r"(r2), "=r"(r3) : "r"(addr));
}

__device__ __forceinline__ void cp_async16(uint32_t dst, const void* src, int src_bytes) {
    asm volatile("cp.async.cg.shared.global [%0], [%1], 16, %2;"
                 :: "r"(dst), "l"(src), "r"(src_bytes) : "memory");
}
#define CP_COMMIT() asm volatile("cp.async.commit_group;" ::: "memory")
#define CP_WAIT(n)  asm volatile("cp.async.wait_group %0;" :: "n"(n) : "memory")

// ---------------- K0: zero g_c + out + counts, build pair table (block 0) ----------------
__global__ void zero_kernel(float* __restrict__ out) {
    size_t idx = (size_t)blockIdx.x * blockDim.x + threadIdx.x;
    float4* c4 = reinterpret_cast<float4*>(g_c);
    c4[idx] = make_float4(0.f, 0.f, 0.f, 0.f);
    if (idx < N_STRUCT) out[idx] = 0.f;
    if (idx < N_SPECIES) g_counts[idx] = 0;
    if (blockIdx.x == 0) {
        for (int i = threadIdx.x; i < NPAIR; i += blockDim.x) {
            int q = 0, off = 0;
            while (off + (Q_DIM - q) <= i) { off += Q_DIM - q; q++; }
            g_pairq[i] = q;
            g_pairp[i] = q + (i - off);
        }
    }
}

// ---------------- K1 ----------------
__global__ void atom_prep_kernel(const int* __restrict__ numbers,
                                 const int* __restrict__ batch,
                                 const float* __restrict__ Wc,
                                 float* __restrict__ out) {
    int a = blockIdx.x * blockDim.x + threadIdx.x;
    if (a >= N_ATOMS) return;
    int s = numbers[a];
    atomicAdd(&g_counts[s], 1);
    atomicAdd(&out[batch[a]], Wc[s]);
}

// ---------------- K2: scan only ----------------
__global__ void offsets_kernel() {
    if (threadIdx.x == 0) {
        int acc = 0;
        for (int s = 0; s < N_SPECIES; s++) {
            g_off[s] = acc;
            g_cursor[s] = acc;
            acc += g_counts[s];
        }
    }
}

// ---------------- K3 ----------------
__global__ void scatter_kernel(const int* __restrict__ numbers) {
    int a = blockIdx.x * blockDim.x + threadIdx.x;
    if (a >= N_ATOMS) return;
    int s = numbers[a];
    int pos = atomicAdd(&g_cursor[s], 1);
    g_sorted[pos] = a;
}

// ---------------- K3b: fold W1 + transpose + split (pair-major K layout) ----------------
// Output K index kk = pr*4 + l  (matches ps_kernel's pair-major store order).
__global__ void fold_w1_kernel(const float* __restrict__ W1) {
    __shared__ float tile[32][33];
    int tx = threadIdx.x, ty = threadIdx.y;
    int k = blockIdx.x * 32 + ty;          // K index in pair-major layout
    int n = blockIdx.y * 32 + tx;
    int pr = k >> 2;
    int l  = k & 3;
    int q = g_pairq[pr], p = g_pairp[pr];
    const float* Ws = W1 + (size_t)blockIdx.z * PS_DIM * HID;
    float v = Ws[(size_t)(l * 1024 + q * 32 + p) * HID + n];
    if (q != p)
        v += Ws[(size_t)(l * 1024 + p * 32 + q) * HID + n];
    tile[ty][tx] = v;
    __syncthreads();
    int nn = blockIdx.y * 32 + ty;
    int kk = blockIdx.x * 32 + tx;
    float w = tile[tx][ty];
    __nv_bfloat16 h = __float2bfloat16_rn(w);
    size_t oi = ((size_t)(blockIdx.z * HID + nn)) * PS_SYM + kk;
    g_w1h[oi] = h;
    g_w1l[oi] = __float2bfloat16_rn(w - __bfloat162float(h));
}

// ---------------- K3c: W2 transpose + split ----------------
__global__ void fold_w2_kernel(const float* __restrict__ W2) {
    __shared__ float tile[32][33];
    int tx = threadIdx.x, ty = threadIdx.y;
    int k = blockIdx.x * 32 + ty;
    int n = blockIdx.y * 32 + tx;
    tile[ty][tx] = W2[((size_t)(blockIdx.z * HID + k)) * HID + n];
    __syncthreads();
    int nn = blockIdx.y * 32 + ty;
    int kk = blockIdx.x * 32 + tx;
    float w = tile[tx][ty];
    __nv_bfloat16 h = __float2bfloat16_rn(w);
    size_t oi = ((size_t)(blockIdx.z * HID + nn)) * HID + kk;
    g_w2h[oi] = h;
    g_w2l[oi] = __float2bfloat16_rn(w - __bfloat162float(h));
}

// ---------------- K4: edge featurization ----------------
__global__ void edge_kernel(const float* __restrict__ pos,
                            const float* __restrict__ cells,
                            const int* __restrict__ numbers,
                            const int* __restrict__ ei,
                            const int* __restrict__ eoff,
                            const int* __restrict__ batch) {
    int e = blockIdx.x * blockDim.x + threadIdx.x;
    if (e >= N_EDGES) return;
    int i = ei[e];
    int j = ei[N_EDGES + e];

    float pix = pos[3*i+0], piy = pos[3*i+1], piz = pos[3*i+2];
    float pjx = pos[3*j+0], pjy = pos[3*j+1], pjz = pos[3*j+2];

    int o0 = eoff[3*e+0], o1 = eoff[3*e+1], o2 = eoff[3*e+2];
    float sx = 0.f, sy = 0.f, sz = 0.f;
    if (o0 | o1 | o2) {
        int b = batch[i];
        const float* cb = cells + (size_t)b * 9;
        float f0 = (float)o0, f1 = (float)o1, f2 = (float)o2;
        sx = f0*cb[0] + f1*cb[3] + f2*cb[6];
        sy = f0*cb[1] + f1*cb[4] + f2*cb[7];
        sz = f0*cb[2] + f1*cb[5] + f2*cb[8];
    }

    float dx = pjx - pix + sx;
    float dy = pjy - piy + sy;
    float dz = pjz - piz + sz;
    float r2 = dx*dx + dy*dy + dz*dz + EPSR;
    float r  = sqrtf(r2);
    if (r >= CUTOFF) return;

    float inv = 1.0f / r;
    float a_c = r * (1.0f / CUTOFF);
    float fc  = 0.5f * (cospif(a_c) + 1.0f);
    float x = dx * inv, y = dy * inv, z = dz * inv;
    float x2 = x*x, y2 = y*y, z2 = z*z;

    float Y[16];
    Y[0]  = 0.28209479177387814f;
    Y[1]  = 0.4886025119029199f * y;
    Y[2]  = 0.4886025119029199f * z;
    Y[3]  = 0.4886025119029199f * x;
    Y[4]  = 1.0925484305920792f * x * y;
    Y[5]  = 1.0925484305920792f * y * z;
    Y[6]  = 0.31539156525252005f * (3.0f*z2 - 1.0f);
    Y[7]  = 1.0925484305920792f * x * z;
    Y[8]  = 0.5462742152960396f * (x2 - y2);
    Y[9]  = 0.5900435899266435f * y * (3.0f*x2 - y2);
    Y[10] = 2.890611442640554f  * x * y * z;
    Y[11] = 0.4570457994644658f * y * (5.0f*z2 - 1.0f);
    Y[12] = 0.3731763325901154f * z * (5.0f*z2 - 3.0f);
    Y[13] = 0.4570457994644658f * x * (5.0f*z2 - 1.0f);
    Y[14] = 1.445305721320277f  * z * (x2 - y2);
    Y[15] = 0.5900435899266435f * x * (x2 - 3.0f*y2);

    float rn[N_RADIAL];
    float scale = inv * fc;
    #pragma unroll
    for (int n = 0; n < N_RADIAL; n++)
        rn[n] = sinpif((float)(n + 1) * a_c) * scale;

    int sj = numbers[j];
    float* base = g_c + ((size_t)i * N_SPECIES + sj) * (N_RADIAL * N_SPH);

    #pragma unroll
    for (int n = 0; n < N_RADIAL; n++) {
        float rv = rn[n];
        #pragma unroll
        for (int m4 = 0; m4 < 4; m4++) {
            red4(base + n*16 + m4*4,
                 rv * Y[m4*4 + 0], rv * Y[m4*4 + 1],
                 rv * Y[m4*4 + 2], rv * Y[m4*4 + 3]);
        }
    }
}

// ---------------- K5: power spectrum, pair-major output (STG.64 x2 per pair) ----------------
__global__ void ps_kernel() {
    __shared__ float cs[N_SPH][Q_DIM + 1];
    __shared__ int   pq[NPAIR];
    __shared__ int   pp[NPAIR];
    int a = blockIdx.x;
    int t = threadIdx.x;      // 128
    {
        const float4* ca = reinterpret_cast<const float4*>(g_c + (size_t)a * C_PER_ATOM);
        float4 v = ca[t];
        int q = t >> 2;
        int m = (t & 3) * 4;
        cs[m + 0][q] = v.x;
        cs[m + 1][q] = v.y;
        cs[m + 2][q] = v.z;
        cs[m + 3][q] = v.w;
    }
    for (int i = t; i < NPAIR; i += 128) {
        pq[i] = g_pairq[i];
        pp[i] = g_pairp[i];
    }
    __syncthreads();

    uint64_t* oh = reinterpret_cast<uint64_t*>(g_psh + (size_t)a * PS_SYM);
    uint64_t* ol = reinterpret_cast<uint64_t*>(g_psl + (size_t)a * PS_SYM);

    #pragma unroll
    for (int base = 0; base < NPAIR; base += 128) {
        int pr = base + t;
        if (pr >= NPAIR) break;
        int q = pq[pr], p = pp[pr];

        float s0, s1 = 0.f, s2 = 0.f, s3 = 0.f;
        s0 = cs[0][q] * cs[0][p];
        #pragma unroll
        for (int m = 1; m < 4; m++)  s1 += cs[m][q] * cs[m][p];
        #pragma unroll
        for (int m = 4; m < 9; m++)  s2 += cs[m][q] * cs[m][p];
        #pragma unroll
        for (int m = 9; m < 16; m++) s3 += cs[m][q] * cs[m][p];

        s1 *= 0.5773502691896258f;
        s2 *= 0.4472135954999579f;
        s3 *= 0.3779644730092272f;

        __nv_bfloat16 h0 = __float2bfloat16_rn(s0);
        __nv_bfloat16 h1 = __float2bfloat16_rn(s1);
        __nv_bfloat16 h2 = __float2bfloat16_rn(s2);
        __nv_bfloat16 h3 = __float2bfloat16_rn(s3);
        oh[pr] = pack4(h0, h1, h2, h3);
        ol[pr] = pack4(__float2bfloat16_rn(s0 - __bfloat162float(h0)),
                       __float2bfloat16_rn(s1 - __bfloat162float(h1)),
                       __float2bfloat16_rn(s2 - __bfloat162float(h2)),
                       __float2bfloat16_rn(s3 - __bfloat162float(h3)));
    }
}

// ---------------- K6/K7: bf16x3 GEMM, 3-stage ring, fragment-reuse (R14 proven) ----------------
#define KPAD 72
#define STAGE_BF16 (128 * KPAD)
#define STAGE_BYTES (2 * STAGE_BF16 * 2)       // A+B per stage = 36864
#define GEMM_SMEM (3 * STAGE_BYTES)            // 110592 bytes

template<int WHICH>
__global__ void __launch_bounds__(256, 2) gemm_mma_kernel(
        const float* __restrict__ W3,
        const int* __restrict__ batch,
        float* __restrict__ out) {
    constexpr int K  = (WHICH == 1) ? PS_SYM : HID;
    constexpr int NS = K / 32;

    const int item  = blockIdx.x;
    const int tile  = item >> 1;
    const int nbase = (item & 1) * 128;

    int s = -1, mloc = 0, acc = 0;
    #pragma unroll
    for (int sp = 0; sp < N_SPECIES; sp++) {
        int ts = (g_counts[sp] + 127) >> 7;
        if (s < 0 && tile < acc + ts) { s = sp; mloc = (tile - acc) << 7; }
        acc += ts;
    }
    if (s < 0) return;
    const int row0   = g_off[s] + mloc;
    const int mcount = min(128, g_counts[s] - mloc);

    extern __shared__ __nv_bfloat16 smem[];
    __shared__ float w3s[128];
    __shared__ float srow[128];

    const int tid  = threadIdx.x;
    const int wid  = tid >> 5;
    const int lane = tid & 31;
    const int gid  = lane >> 2;
    const int tig  = lane & 3;
    const int wm   = wid & 1;
    const int wn   = wid >> 1;

    if (WHICH == 2) {
        if (tid < 128) {
            w3s[tid] = W3[s * HID + nbase + tid];
            srow[tid] = 0.f;
        }
    }

    const int lrow = tid >> 1;
    const int lh   = (tid & 1) * 16;
    const bool mvalid = (lrow < mcount);
    const int abytes = mvalid ? 16 : 0;
    const __nv_bfloat16* Ahrow = nullptr;
    const __nv_bfloat16* Alrow = nullptr;
    {
        int r = row0 + min(lrow, mcount - 1);
        int src = (WHICH == 1) ? g_sorted[r] : r;
        Ahrow = ((WHICH == 1) ? g_psh : g_h1h) + (size_t)src * K + lh;
        Alrow = ((WHICH == 1) ? g_psl : g_h1l) + (size_t)src * K + lh;
    }
    const __nv_bfloat16* Bhrow =
        ((WHICH == 1) ? g_w1h : g_w2h) + ((size_t)(s * HID + nbase + lrow)) * K + lh;
    const __nv_bfloat16* Blrow =
        ((WHICH == 1) ? g_w1l : g_w2l) + ((size_t)(s * HID + nbase + lrow)) * K + lh;

    const uint32_t smem_sh = (uint32_t)__cvta_generic_to_shared(smem);
    const uint32_t aDst = smem_sh + (lrow * KPAD + lh) * 2;
    const uint32_t bDst = smem_sh + (STAGE_BF16 + lrow * KPAD + lh) * 2;

    auto issue_stage = [&](int kt, int buf) {
        const uint32_t boff = (uint32_t)buf * STAGE_BYTES;
        const int kb = kt * 32;
        cp_async16(aDst + boff,           Ahrow + kb,     abytes);
        cp_async16(aDst + boff + 16,      Ahrow + kb + 8, abytes);
        cp_async16(aDst + boff + 64,      Alrow + kb,     abytes);
        cp_async16(aDst + boff + 64 + 16, Alrow + kb + 8, abytes);
        cp_async16(bDst + boff,           Bhrow + kb,     16);
        cp_async16(bDst + boff + 16,      Bhrow + kb + 8, 16);
        cp_async16(bDst + boff + 64,      Blrow + kb,     16);
        cp_async16(bDst + boff + 64 + 16, Blrow + kb + 8, 16);
        CP_COMMIT();
    };

    float accum[4][4][4];
    #pragma unroll
    for (int i = 0; i < 4; i++)
        #pragma unroll
        for (int j = 0; j < 4; j++)
            #pragma unroll
            for (int e = 0; e < 4; e++) accum[i][j][e] = 0.f;

    uint32_t aOff[4], bOff[2];
    #pragma unroll
    for (int mt = 0; mt < 4; mt++)
        aOff[mt] = (uint32_t)(((wm * 64 + mt * 16 + (lane & 15)) * KPAD
                               + (lane >> 4) * 8) * 2);
    #pragma unroll
    for (int ng = 0; ng < 2; ng++)
        bOff[ng] = (uint32_t)(((wn * 32 + ng * 16 + ((lane >> 4) << 3) + (lane & 7)) * KPAD
                               + ((lane >> 3) & 1) * 8) * 2);

    issue_stage(0, 0);
    if (NS > 1) issue_stage(1, 1);

    int buf = 0;
    for (int kt = 0; kt < NS; kt++) {
        if (kt + 1 < NS) { CP_WAIT(1); } else { CP_WAIT(0); }
        __syncthreads();
        if (kt + 2 < NS) issue_stage(kt + 2, (buf + 2) % 3);

        const uint32_t sA = smem_sh + (uint32_t)buf * STAGE_BYTES;
        const uint32_t sB = sA + STAGE_BF16 * 2;

        #pragma unroll
        for (int kk = 0; kk < 2; kk++) {
            const uint32_t k16 = kk * 16 * 2;
            const uint32_t klo = (32 + kk * 16) * 2;

            uint32_t ah[4][4];
            uint32_t bh0[4], bh1[4];
            ldmatrix_x4(bh0[0], bh0[1], bh0[2], bh0[3], sB + bOff[0] + k16);
            ldmatrix_x4(bh1[0], bh1[1], bh1[2], bh1[3], sB + bOff[1] + k16);
            #pragma unroll
            for (int mt = 0; mt < 4; mt++)
                ldmatrix_x4(ah[mt][0], ah[mt][1], ah[mt][2], ah[mt][3],
                            sA + aOff[mt] + k16);

            #pragma unroll
            for (int mt = 0; mt < 4; mt++) {
                mma_bf16(accum[mt][0][0], accum[mt][0][1], accum[mt][0][2], accum[mt][0][3],
                         ah[mt][0], ah[mt][1], ah[mt][2], ah[mt][3], bh0[0], bh0[1]);
                mma_bf16(accum[mt][1][0], accum[mt][1][1], accum[mt][1][2], accum[mt][1][3],
                         ah[mt][0], ah[mt][1], ah[mt][2], ah[mt][3], bh0[2], bh0[3]);
                mma_bf16(accum[mt][2][0], accum[mt][2][1], accum[mt][2][2], accum[mt][2][3],
                         ah[mt][0], ah[mt][1], ah[mt][2], ah[mt][3], bh1[0], bh1[1]);
                mma_bf16(accum[mt][3][0], accum[mt][3][1], accum[mt][3][2], accum[mt][3][3],
                         ah[mt][0], ah[mt][1], ah[mt][2], ah[mt][3], bh1[2], bh1[3]);
            }

            ldmatrix_x4(bh0[0], bh0[1], bh0[2], bh0[3], sB + bOff[0] + klo);
            ldmatrix_x4(bh1[0], bh1[1], bh1[2], bh1[3], sB + bOff[1] + klo);
            #pragma unroll
            for (int mt = 0; mt < 4; mt++) {
                mma_bf16(accum[mt][0][0], accum[mt][0][1], accum[mt][0][2], accum[mt][0][3],
                         ah[mt][0], ah[mt][1], ah[mt][2], ah[mt][3], bh0[0], bh0[1]);
                mma_bf16(accum[mt][1][0], accum[mt][1][1], accum[mt][1][2], accum[mt][1][3],
                         ah[mt][0], ah[mt][1], ah[mt][2], ah[mt][3], bh0[2], bh0[3]);
                mma_bf16(accum[mt][2][0], accum[mt][2][1], accum[mt][2][2], accum[mt][2][3],
                         ah[mt][0], ah[mt][1], ah[mt][2], ah[mt][3], bh1[0], bh1[1]);
                mma_bf16(accum[mt][3][0], accum[mt][3][1], accum[mt][3][2], accum[mt][3][3],
                         ah[mt][0], ah[mt][1], ah[mt][2], ah[mt][3], bh1[2], bh1[3]);
            }

            ldmatrix_x4(bh0[0], bh0[1], bh0[2], bh0[3], sB + bOff[0] + k16);
            ldmatrix_x4(bh1[0], bh1[1], bh1[2], bh1[3], sB + bOff[1] + k16);
            #pragma unroll
            for (int mt = 0; mt < 4; mt++)
                ldmatrix_x4(ah[mt][0], ah[mt][1], ah[mt][2], ah[mt][3],
                            sA + aOff[mt] + klo);
            #pragma unroll
            for (int mt = 0; mt < 4; mt++) {
                mma_bf16(accum[mt][0][0], accum[mt][0][1], accum[mt][0][2], accum[mt][0][3],
                         ah[mt][0], ah[mt][1], ah[mt][2], ah[mt][3], bh0[0], bh0[1]);
                mma_bf16(accum[mt][1][0], accum[mt][1][1], accum[mt][1][2], accum[mt][1][3],
                         ah[mt][0], ah[mt][1], ah[mt][2], ah[mt][3], bh0[2], bh0[3]);
                mma_bf16(accum[mt][2][0], accum[mt][2][1], accum[mt][2][2], accum[mt][2][3],
                         ah[mt][0], ah[mt][1], ah[mt][2], ah[mt][3], bh1[0], bh1[1]);
                mma_bf16(accum[mt][3][0], accum[mt][3][1], accum[mt][3][2], accum[mt][3][3],
                         ah[mt][0], ah[mt][1], ah[mt][2], ah[mt][3], bh1[2], bh1[3]);
            }
        }
        buf = (buf + 1) % 3;
    }
    __syncthreads();

    if (WHICH == 1) {
        #pragma unroll
        for (int mt = 0; mt < 4; mt++) {
            int r0 = wm * 64 + mt * 16 + gid;
            int r1 = r0 + 8;
            #pragma unroll
            for (int nt = 0; nt < 4; nt++) {
                int col = nbase + wn * 32 + nt * 8 + 2 * tig;
                if (r0 < mcount) {
                    float v0 = silu(accum[mt][nt][0]);
                    float v1 = silu(accum[mt][nt][1]);
                    __nv_bfloat16 h0 = __float2bfloat16_rn(v0);
                    __nv_bfloat16 h1 = __float2bfloat16_rn(v1);
                    size_t o = (size_t)(row0 + r0) * HID + col;
                    *reinterpret_cast<uint32_t*>(&g_h1h[o]) = pack2(h0, h1);
                    *reinterpret_cast<uint32_t*>(&g_h1l[o]) =
                        pack2(__float2bfloat16_rn(v0 - __bfloat162float(h0)),
                              __float2bfloat16_rn(v1 - __bfloat162float(h1)));
                }
                if (r1 < mcount) {
                    float v0 = silu(accum[mt][nt][2]);
                    float v1 = silu(accum[mt][nt][3]);
                    __nv_bfloat16 h0 = __float2bfloat16_rn(v0);
                    __nv_bfloat16 h1 = __float2bfloat16_rn(v1);
                    size_t o = (size_t)(row0 + r1) * HID + col;
                    *reinterpret_cast<uint32_t*>(&g_h1h[o]) = pack2(h0, h1);
                    *reinterpret_cast<uint32_t*>(&g_h1l[o]) =
                        pack2(__float2bfloat16_rn(v0 - __bfloat162float(h0)),
                              __float2bfloat16_rn(v1 - __bfloat162float(h1)));
                }
            }
        }
    } else {
        #pragma unroll
        for (int mt = 0; mt < 4; mt++) {
            int r0 = wm * 64 + mt * 16 + gid;
            float p0 = 0.f, p1 = 0.f;
            #pragma unroll
            for (int nt = 0; nt < 4; nt++) {
                int col = wn * 32 + nt * 8 + 2 * tig;
                float wa = w3s[col], wb = w3s[col + 1];
                p0 += silu(accum[mt][nt][0]) * wa + silu(accum[mt][nt][1]) * wb;
                p1 += silu(accum[mt][nt][2]) * wa + silu(accum[mt][nt][3]) * wb;
            }
            #pragma unroll
            for (int o = 1; o < 4; o <<= 1) {
                p0 += __shfl_xor_sync(0xFFFFFFFFu, p0, o);
                p1 += __shfl_xor_sync(0xFFFFFFFFu, p1, o);
            }
            if (tig == 0) {
                atomicAdd(&srow[r0], p0);
                atomicAdd(&srow[r0 + 8], p1);
            }
        }
        __syncthreads();
        if (tid < 128 && tid < mcount) {
            int a = g_sorted[row0 + tid];
            atomicAdd(&out[batch[a]], srow[tid]);
        }
    }
}

// ---------------- launch ----------------
extern "C" void kernel_launch(void* const* d_in, const int* in_sizes, int n_in,
                              void* d_out, int out_size) {
    const float* positions    = (const float*)d_in[0];
    const float* cells        = (const float*)d_in[1];
    const int*   numbers      = (const int*)  d_in[2];
    const int*   edge_indices = (const int*)  d_in[3];
    const int*   edge_offsets = (const int*)  d_in[4];
    const int*   batch        = (const int*)  d_in[5];
    const float* Wc           = (const float*)d_in[6];
    const float* W1           = (const float*)d_in[7];
    const float* W2           = (const float*)d_in[8];
    const float* W3           = (const float*)d_in[9];
    float* out = (float*)d_out;

    cudaFuncSetAttribute(gemm_mma_kernel<1>,
                         cudaFuncAttributeMaxDynamicSharedMemorySize, GEMM_SMEM);
    cudaFuncSetAttribute(gemm_mma_kernel<2>,
                         cudaFuncAttributeMaxDynamicSharedMemorySize, GEMM_SMEM);

    zero_kernel<<<10000, 256>>>(out);
    atom_prep_kernel<<<(N_ATOMS + 255) / 256, 256>>>(numbers, batch, Wc, out);
    offsets_kernel<<<1, 32>>>();
    edge_kernel<<<N_EDGES / 256, 256>>>(positions, cells, numbers,
                                        edge_indices, edge_offsets, batch);
    ps_kernel<<<N_ATOMS, 128>>>();
    scatter_kernel<<<(N_ATOMS + 255) / 256, 256>>>(numbers);
    fold_w1_kernel<<<dim3(66, 8, 4), dim3(32, 32)>>>(W1);
    fold_w2_kernel<<<dim3(8, 8, 4), dim3(32, 32)>>>(W2);
    gemm_mma_kernel<1><<<MAX_TILES * 2, 256, GEMM_SMEM>>>(W3, batch, out);
    gemm_mma_kernel<2><<<MAX_TILES * 2, 256, GEMM_SMEM>>>(W3, batch, out);
}